// round 10
// baseline (speedup 1.0000x reference)
#include <cuda_runtime.h>
#include <cuda_fp16.h>
#include <math.h>
#include <stdint.h>

#define NGN 12331
#define NDN 5000
#define EGG 1000000
#define EGD 400000
#define EDD 100000

// ---------------- scratch (device globals; no allocation allowed) ----------------
__device__ int g_cnt_gg_src[NGN], g_cnt_gg_dst[NGN], g_cnt_gd_src[NGN];
__device__ int g_cnt_gd_dst[NDN], g_cnt_dd_src[NDN], g_cnt_dd_dst[NDN];
__device__ int g_rp_gg[NGN + 1], g_rp_dg[NGN + 1], g_rp_gd[NDN + 1], g_rp_dd[NDN + 1];
__device__ int g_fill_gg[NGN], g_fill_dg[NGN], g_fill_gd[NDN], g_fill_dd[NDN];
__device__ int g_col_gg[EGG], g_col_dg[EGD], g_col_gd[EGD], g_col_dd[EDD];
__device__ float g_rs_gg_src[NGN], g_rs_gg_dst[NGN], g_rs_gd_src[NGN];
__device__ float g_rs_gd_dst[NDN], g_rs_dd_src[NDN], g_rs_dd_dst[NDN];
__device__ __align__(256) float g_hg[NGN * 64];
__device__ __align__(256) float g_hd[NDN * 64];   // reused late as bh/bl (fp16 pair, 640KB < 1.28MB)
__device__ __align__(256) __half g_xga[NGN * 64], g_xgb[NGN * 64];
__device__ __align__(256) __half g_xda[NDN * 64], g_xdb[NDN * 64];
__device__ __align__(256) __half g_ah[NGN * 32];
__device__ __align__(256) float g_og[NGN * 64];
__device__ __align__(256) float g_od[NDN * 64];

// ---------------- setup ----------------
__global__ void k_zero_counts() {
    int i = blockIdx.x * blockDim.x + threadIdx.x;
    if (i < NGN) { g_cnt_gg_src[i] = 0; g_cnt_gg_dst[i] = 0; g_cnt_gd_src[i] = 0; }
    if (i < NDN) { g_cnt_gd_dst[i] = 0; g_cnt_dd_src[i] = 0; g_cnt_dd_dst[i] = 0; }
}

// ---- merged launch: blocks [0,histBlocks) = degree histogram; rest = embeddings ----
__global__ __launch_bounds__(256) void k_hist_embed(
    const int* __restrict__ gg_s, const int* __restrict__ gg_d,
    const int* __restrict__ gd_s, const int* __restrict__ gd_d,
    const int* __restrict__ dd_s, const int* __restrict__ dd_d,
    int ngg, int ngd, int ndd, int histBlocks,
    const float* __restrict__ Fg, const float* __restrict__ Wg, float* __restrict__ Hg, int ng,
    const float* __restrict__ Fd, const float* __restrict__ Wd, float* __restrict__ Hd, int nd,
    int gblocks)
{
    constexpr int RPW = 4;
    __shared__ float Wt[64][64];
    __shared__ float hs[8][RPW][64];

    if ((int)blockIdx.x < histBlocks) {
        const int total = ngg + ngd + ndd;
        const int stride = histBlocks * blockDim.x;
        for (int i = blockIdx.x * blockDim.x + threadIdx.x; i < total; i += stride) {
            if (i < ngg) {
                atomicAdd(&g_cnt_gg_src[gg_s[i]], 1);
                atomicAdd(&g_cnt_gg_dst[gg_d[i]], 1);
            } else if (i < ngg + ngd) {
                int j = i - ngg;
                atomicAdd(&g_cnt_gd_src[gd_s[j]], 1);
                atomicAdd(&g_cnt_gd_dst[gd_d[j]], 1);
            } else {
                int j = i - ngg - ngd;
                atomicAdd(&g_cnt_dd_src[dd_s[j]], 1);
                atomicAdd(&g_cnt_dd_dst[dd_d[j]], 1);
            }
        }
        return;
    }
    // ---- embedding part ----
    int ebid = blockIdx.x - histBlocks;
    const float *F, *W; float* H; int n, bid;
    if (ebid < gblocks) { F = Fg; W = Wg; H = Hg; n = ng; bid = ebid; }
    else                { F = Fd; W = Wd; H = Hd; n = nd; bid = ebid - gblocks; }
    const int warp = threadIdx.x >> 5, lane = threadIdx.x & 31;
    const int base = bid * 8 * RPW;
    float acc[RPW][2];
    #pragma unroll
    for (int i = 0; i < RPW; i++) { acc[i][0] = 0.f; acc[i][1] = 0.f; }
    for (int c = 0; c < 8; c++) {
        __syncthreads();
        for (int i = threadIdx.x; i < 64 * 64; i += 256) {
            int k = i >> 6, o = i & 63;
            Wt[k][o] = W[(size_t)o * 512 + c * 64 + k];
        }
        #pragma unroll
        for (int rr = 0; rr < RPW; rr++) {
            int r = base + warp * RPW + rr;
            if (r < n) {
                hs[warp][rr][lane]      = F[(size_t)r * 512 + c * 64 + lane];
                hs[warp][rr][lane + 32] = F[(size_t)r * 512 + c * 64 + lane + 32];
            }
        }
        __syncthreads();
        #pragma unroll
        for (int k = 0; k < 64; k++) {
            float w0 = Wt[k][lane], w1 = Wt[k][lane + 32];
            #pragma unroll
            for (int rr = 0; rr < RPW; rr++) {
                float h = hs[warp][rr][k];
                acc[rr][0] = fmaf(h, w0, acc[rr][0]);
                acc[rr][1] = fmaf(h, w1, acc[rr][1]);
            }
        }
    }
    #pragma unroll
    for (int rr = 0; rr < RPW; rr++) {
        int r = base + warp * RPW + rr;
        if (r < n) {
            H[(size_t)r * 64 + lane]      = acc[rr][0];
            H[(size_t)r * 64 + lane + 32] = acc[rr][1];
        }
    }
}

// blocks 0..3: 4 single-block exclusive scans; blocks 4+: rsqrt of all degree arrays
__global__ void k_setup2() {
    __shared__ int warp_tot[32];
    if (blockIdx.x >= 4) {
        int i = (blockIdx.x - 4) * 1024 + threadIdx.x;
        if (i < NGN) {
            g_rs_gg_src[i] = rsqrtf((float)max(g_cnt_gg_src[i], 1));
            g_rs_gg_dst[i] = rsqrtf((float)max(g_cnt_gg_dst[i], 1));
            g_rs_gd_src[i] = rsqrtf((float)max(g_cnt_gd_src[i], 1));
        }
        if (i < NDN) {
            g_rs_gd_dst[i] = rsqrtf((float)max(g_cnt_gd_dst[i], 1));
            g_rs_dd_src[i] = rsqrtf((float)max(g_cnt_dd_src[i], 1));
            g_rs_dd_dst[i] = rsqrtf((float)max(g_cnt_dd_dst[i], 1));
        }
        return;
    }
    const int* cnt; int* rp; int* fill; int n;
    if (blockIdx.x == 0)      { cnt = g_cnt_gg_dst; rp = g_rp_gg; fill = g_fill_gg; n = NGN; }
    else if (blockIdx.x == 1) { cnt = g_cnt_gd_src; rp = g_rp_dg; fill = g_fill_dg; n = NGN; }
    else if (blockIdx.x == 2) { cnt = g_cnt_gd_dst; rp = g_rp_gd; fill = g_fill_gd; n = NDN; }
    else                      { cnt = g_cnt_dd_dst; rp = g_rp_dd; fill = g_fill_dd; n = NDN; }
    const int t = threadIdx.x;
    const int lane = t & 31, w = t >> 5;
    const int C = (n + 1023) / 1024;
    int lo = t * C, hi = min((t + 1) * C, n);
    int s = 0;
    for (int i = lo; i < hi; i++) s += cnt[i];
    int v = s;
    #pragma unroll
    for (int o = 1; o < 32; o <<= 1) {
        int u = __shfl_up_sync(0xFFFFFFFFu, v, o);
        if (lane >= o) v += u;
    }
    if (lane == 31) warp_tot[w] = v;
    __syncthreads();
    if (w == 0) {
        int x = warp_tot[lane];
        #pragma unroll
        for (int o = 1; o < 32; o <<= 1) {
            int u = __shfl_up_sync(0xFFFFFFFFu, x, o);
            if (lane >= o) x += u;
        }
        warp_tot[lane] = x;
    }
    __syncthreads();
    int run = v - s + (w > 0 ? warp_tot[w - 1] : 0);  // exclusive prefix
    for (int i = lo; i < hi; i++) { int c = cnt[i]; rp[i] = run; fill[i] = run; run += c; }
    if (t == 1023) rp[n] = run;
}

// ---- merged launch: blocks [0,scatBlocks) = CSR fill; rest = layer-1 dual transform ----
__global__ __launch_bounds__(256) void k_scatter_t2(
    const int* __restrict__ gg_s, const int* __restrict__ gg_d,
    const int* __restrict__ gd_s, const int* __restrict__ gd_d,
    const int* __restrict__ dd_s, const int* __restrict__ dd_d,
    int ngg, int ngd, int ndd, int scatBlocks,
    const float* __restrict__ Hg,
    const float* __restrict__ sGA, const float* __restrict__ WGA,
    const float* __restrict__ sGB, const float* __restrict__ WGB,
    __half* __restrict__ XGA, __half* __restrict__ XGB, int ng,
    const float* __restrict__ Hd,
    const float* __restrict__ sDA, const float* __restrict__ WDA,
    const float* __restrict__ sDB, const float* __restrict__ WDB,
    __half* __restrict__ XDA, __half* __restrict__ XDB, int nd,
    int gblocks)
{
    constexpr int RPW = 2;
    __shared__ float WtA[64][64];
    __shared__ float WtB[64][64];
    __shared__ float hs[8][RPW][64];

    if ((int)blockIdx.x < scatBlocks) {
        const int total = ngg + ngd + ndd;
        const int stride = scatBlocks * blockDim.x;
        for (int i = blockIdx.x * blockDim.x + threadIdx.x; i < total; i += stride) {
            if (i < ngg) {
                int r = gg_d[i];
                int p = atomicAdd(&g_fill_gg[r], 1);
                g_col_gg[p] = gg_s[i];
            } else if (i < ngg + ngd) {
                int j = i - ngg;
                int s = gd_s[j], d = gd_d[j];
                int p = atomicAdd(&g_fill_dg[s], 1);  // reversed: disease->gene
                g_col_dg[p] = d;
                int q = atomicAdd(&g_fill_gd[d], 1);  // gene->disease
                g_col_gd[q] = s;
            } else {
                int j = i - ngg - ngd;
                int r = dd_d[j];
                int p = atomicAdd(&g_fill_dd[r], 1);
                g_col_dd[p] = dd_s[j];
            }
        }
        return;
    }
    // ---- layer-1 dual transform (DOUT=64) ----
    int ebid = blockIdx.x - scatBlocks;
    const float *H, *scA, *WA, *scB, *WB; __half *XA, *XB; int n, bid;
    if (ebid < gblocks) {
        H = Hg; scA = sGA; WA = WGA; scB = sGB; WB = WGB; XA = XGA; XB = XGB;
        n = ng; bid = ebid;
    } else {
        H = Hd; scA = sDA; WA = WDA; scB = sDB; WB = WDB; XA = XDA; XB = XDB;
        n = nd; bid = ebid - gblocks;
    }
    const int warp = threadIdx.x >> 5, lane = threadIdx.x & 31;
    const int base = bid * 8 * RPW;
    for (int i = threadIdx.x; i < 64 * 64; i += 256) {
        int k = i >> 6, o = i & 63;
        WtA[k][o] = WA[(size_t)o * 64 + k];
        WtB[k][o] = WB[(size_t)o * 64 + k];
    }
    #pragma unroll
    for (int rr = 0; rr < RPW; rr++) {
        int r = base + warp * RPW + rr;
        if (r < n) {
            hs[warp][rr][lane]      = H[(size_t)r * 64 + lane];
            hs[warp][rr][lane + 32] = H[(size_t)r * 64 + lane + 32];
        }
    }
    __syncthreads();
    float aA[RPW][2], aB[RPW][2];
    #pragma unroll
    for (int i = 0; i < RPW; i++) { aA[i][0] = aA[i][1] = 0.f; aB[i][0] = aB[i][1] = 0.f; }
    #pragma unroll
    for (int k = 0; k < 64; k++) {
        float wa0 = WtA[k][lane], wb0 = WtB[k][lane];
        float wa1 = WtA[k][lane + 32], wb1 = WtB[k][lane + 32];
        #pragma unroll
        for (int rr = 0; rr < RPW; rr++) {
            float h = hs[warp][rr][k];
            aA[rr][0] = fmaf(h, wa0, aA[rr][0]);
            aB[rr][0] = fmaf(h, wb0, aB[rr][0]);
            aA[rr][1] = fmaf(h, wa1, aA[rr][1]);
            aB[rr][1] = fmaf(h, wb1, aB[rr][1]);
        }
    }
    #pragma unroll
    for (int rr = 0; rr < RPW; rr++) {
        int r = base + warp * RPW + rr;
        if (r < n) {
            float sA = scA[r], sB = scB[r];
            XA[(size_t)r * 64 + lane]      = __float2half_rn(aA[rr][0] * sA);
            XB[(size_t)r * 64 + lane]      = __float2half_rn(aB[rr][0] * sB);
            XA[(size_t)r * 64 + lane + 32] = __float2half_rn(aA[rr][1] * sA);
            XB[(size_t)r * 64 + lane + 32] = __float2half_rn(aB[rr][1] * sB);
        }
    }
}

// -------- layer-2 dual transform (DOUT=32), both node types, standalone --------
__global__ __launch_bounds__(256) void k_t2_pair32(
    const float* __restrict__ Hg,
    const float* __restrict__ sGA, const float* __restrict__ WGA,
    const float* __restrict__ sGB, const float* __restrict__ WGB,
    __half* __restrict__ XGA, __half* __restrict__ XGB, int ng,
    const float* __restrict__ Hd,
    const float* __restrict__ sDA, const float* __restrict__ WDA,
    const float* __restrict__ sDB, const float* __restrict__ WDB,
    __half* __restrict__ XDA, __half* __restrict__ XDB, int nd,
    int gblocks)
{
    constexpr int RPW = 2;
    __shared__ float WtA[64][32];
    __shared__ float WtB[64][32];
    __shared__ float hs[8][RPW][64];
    const float *H, *scA, *WA, *scB, *WB; __half *XA, *XB; int n, bid;
    if (blockIdx.x < gblocks) {
        H = Hg; scA = sGA; WA = WGA; scB = sGB; WB = WGB; XA = XGA; XB = XGB;
        n = ng; bid = blockIdx.x;
    } else {
        H = Hd; scA = sDA; WA = WDA; scB = sDB; WB = WDB; XA = XDA; XB = XDB;
        n = nd; bid = blockIdx.x - gblocks;
    }
    const int warp = threadIdx.x >> 5, lane = threadIdx.x & 31;
    const int base = bid * 8 * RPW;
    for (int i = threadIdx.x; i < 64 * 32; i += 256) {
        int k = i >> 5, o = i & 31;
        WtA[k][o] = WA[(size_t)o * 64 + k];
        WtB[k][o] = WB[(size_t)o * 64 + k];
    }
    #pragma unroll
    for (int rr = 0; rr < RPW; rr++) {
        int r = base + warp * RPW + rr;
        if (r < n) {
            hs[warp][rr][lane]      = H[(size_t)r * 64 + lane];
            hs[warp][rr][lane + 32] = H[(size_t)r * 64 + lane + 32];
        }
    }
    __syncthreads();
    float aA[RPW], aB[RPW];
    #pragma unroll
    for (int i = 0; i < RPW; i++) { aA[i] = 0.f; aB[i] = 0.f; }
    #pragma unroll
    for (int k = 0; k < 64; k++) {
        float wa = WtA[k][lane], wb = WtB[k][lane];
        #pragma unroll
        for (int rr = 0; rr < RPW; rr++) {
            float h = hs[warp][rr][k];
            aA[rr] = fmaf(h, wa, aA[rr]);
            aB[rr] = fmaf(h, wb, aB[rr]);
        }
    }
    #pragma unroll
    for (int rr = 0; rr < RPW; rr++) {
        int r = base + warp * RPW + rr;
        if (r < n) {
            XA[(size_t)r * 32 + lane] = __float2half_rn(aA[rr] * scA[r]);
            XB[(size_t)r * 32 + lane] = __float2half_rn(aB[rr] * scB[r]);
        }
    }
}

// ------- vectorized CSR gather-sum: LDG.64, up to 8 outstanding loads/warp -------
// after the xor-reduce, EVERY lane holds the full sum for dims [4d..4d+3], d = lane % (DOUT/4)
template <int DOUT>
__device__ __forceinline__ float4 agg_one(const int* __restrict__ rp, const int* __restrict__ col,
                                          const __half* __restrict__ x, int v, int lane)
{
    constexpr int LPE = DOUT / 4;   // lanes per edge (16 for D64, 8 for D32)
    constexpr int EPW = 32 / LPE;   // edges per warp step (2 or 4)
    const int sub = lane / LPE;
    const int d = lane - sub * LPE;
    const __half* base = x + d * 4;
    float4 acc = make_float4(0.f, 0.f, 0.f, 0.f);
    int s = rp[v], e = rp[v + 1], j = s;
    for (; j + 4 * EPW <= e; j += 4 * EPW) {
        int u0 = col[j + sub];
        int u1 = col[j + EPW + sub];
        int u2 = col[j + 2 * EPW + sub];
        int u3 = col[j + 3 * EPW + sub];
        uint2 r0 = *(const uint2*)(base + (size_t)u0 * DOUT);
        uint2 r1 = *(const uint2*)(base + (size_t)u1 * DOUT);
        uint2 r2 = *(const uint2*)(base + (size_t)u2 * DOUT);
        uint2 r3 = *(const uint2*)(base + (size_t)u3 * DOUT);
        float2 a0 = __half22float2(*reinterpret_cast<__half2*>(&r0.x));
        float2 a1 = __half22float2(*reinterpret_cast<__half2*>(&r0.y));
        float2 b0 = __half22float2(*reinterpret_cast<__half2*>(&r1.x));
        float2 b1 = __half22float2(*reinterpret_cast<__half2*>(&r1.y));
        float2 c0 = __half22float2(*reinterpret_cast<__half2*>(&r2.x));
        float2 c1 = __half22float2(*reinterpret_cast<__half2*>(&r2.y));
        float2 d0 = __half22float2(*reinterpret_cast<__half2*>(&r3.x));
        float2 d1 = __half22float2(*reinterpret_cast<__half2*>(&r3.y));
        acc.x += (a0.x + b0.x) + (c0.x + d0.x);
        acc.y += (a0.y + b0.y) + (c0.y + d0.y);
        acc.z += (a1.x + b1.x) + (c1.x + d1.x);
        acc.w += (a1.y + b1.y) + (c1.y + d1.y);
    }
    for (; j + EPW <= e; j += EPW) {
        int u = col[j + sub];
        uint2 r0 = *(const uint2*)(base + (size_t)u * DOUT);
        float2 a0 = __half22float2(*reinterpret_cast<__half2*>(&r0.x));
        float2 a1 = __half22float2(*reinterpret_cast<__half2*>(&r0.y));
        acc.x += a0.x; acc.y += a0.y; acc.z += a1.x; acc.w += a1.y;
    }
    if (j + sub < e) {
        int u = col[j + sub];
        uint2 r0 = *(const uint2*)(base + (size_t)u * DOUT);
        float2 a0 = __half22float2(*reinterpret_cast<__half2*>(&r0.x));
        float2 a1 = __half22float2(*reinterpret_cast<__half2*>(&r0.y));
        acc.x += a0.x; acc.y += a0.y; acc.z += a1.x; acc.w += a1.y;
    }
    #pragma unroll
    for (int off = LPE; off < 32; off <<= 1) {
        acc.x += __shfl_xor_sync(0xFFFFFFFFu, acc.x, off);
        acc.y += __shfl_xor_sync(0xFFFFFFFFu, acc.y, off);
        acc.z += __shfl_xor_sync(0xFFFFFFFFu, acc.z, off);
        acc.w += __shfl_xor_sync(0xFFFFFFFFu, acc.w, off);
    }
    return acc;
}

// ------- layer-1 dual-relation aggregation, both node types, fp32 out -------
__global__ __launch_bounds__(256) void k_agg_pair64(
    const int* __restrict__ rpGA, const int* __restrict__ colGA,
    const __half* __restrict__ xGA, const float* __restrict__ ndGA,
    const int* __restrict__ rpGB, const int* __restrict__ colGB,
    const __half* __restrict__ xGB, const float* __restrict__ ndGB,
    const float* __restrict__ bGA, const float* __restrict__ bGB,
    float* __restrict__ outG, int ng,
    const int* __restrict__ rpDA, const int* __restrict__ colDA,
    const __half* __restrict__ xDA, const float* __restrict__ ndDA,
    const int* __restrict__ rpDB, const int* __restrict__ colDB,
    const __half* __restrict__ xDB, const float* __restrict__ ndDB,
    const float* __restrict__ bDA, const float* __restrict__ bDB,
    float* __restrict__ outD, int nd, int gblocks)
{
    const int warp = threadIdx.x >> 5, lane = threadIdx.x & 31;
    const bool gene = (int)blockIdx.x < gblocks;
    const int bid = gene ? blockIdx.x : blockIdx.x - gblocks;
    const int v = bid * 8 + warp;
    const int* rpA  = gene ? rpGA : rpDA;  const int* colA = gene ? colGA : colDA;
    const __half* xA = gene ? xGA : xDA;   const float* ndA = gene ? ndGA : ndDA;
    const int* rpB  = gene ? rpGB : rpDB;  const int* colB = gene ? colGB : colDB;
    const __half* xB = gene ? xGB : xDB;   const float* ndB = gene ? ndGB : ndDB;
    const float* bA = gene ? bGA : bDA;    const float* bB = gene ? bGB : bDB;
    float* out = gene ? outG : outD;
    const int n = gene ? ng : nd;
    if (v >= n) return;
    float4 aA = agg_one<64>(rpA, colA, xA, v, lane);
    float4 aB = agg_one<64>(rpB, colB, xB, v, lane);
    if (lane < 16) {
        float nA = ndA[v], nB = ndB[v];
        float4 bAv = *(const float4*)(bA + 4 * lane);
        float4 bBv = *(const float4*)(bB + 4 * lane);
        float4 o;
        o.x = fmaxf(nA * aA.x + nB * aB.x + bAv.x + bBv.x, 0.f);
        o.y = fmaxf(nA * aA.y + nB * aB.y + bAv.y + bBv.y, 0.f);
        o.z = fmaxf(nA * aA.z + nB * aB.z + bAv.z + bBv.z, 0.f);
        o.w = fmaxf(nA * aA.w + nB * aB.w + bAv.w + bBv.w, 0.f);
        *(float4*)(out + (size_t)v * 64 + 4 * lane) = o;
    }
}

// ------- layer-2 aggregation: gene -> split-fp16 (Ah,Al); disease -> fused @Wout -> (Bh,Bl) -------
__global__ __launch_bounds__(256) void k_agg_pair32_final(
    const int* __restrict__ rpGA, const int* __restrict__ colGA,
    const __half* __restrict__ xGA, const float* __restrict__ ndGA,
    const int* __restrict__ rpGB, const int* __restrict__ colGB,
    const __half* __restrict__ xGB, const float* __restrict__ ndGB,
    const float* __restrict__ bGA, const float* __restrict__ bGB,
    __half* __restrict__ outAh, __half* __restrict__ outAl, int ng,
    const int* __restrict__ rpDA, const int* __restrict__ colDA,
    const __half* __restrict__ xDA, const float* __restrict__ ndDA,
    const int* __restrict__ rpDB, const int* __restrict__ colDB,
    const __half* __restrict__ xDB, const float* __restrict__ ndDB,
    const float* __restrict__ bDA, const float* __restrict__ bDB,
    const float* __restrict__ Wout,
    __half* __restrict__ outBh, __half* __restrict__ outBl, int nd, int gblocks)
{
    const int warp = threadIdx.x >> 5, lane = threadIdx.x & 31;
    const bool gene = (int)blockIdx.x < gblocks;
    const int bid = gene ? blockIdx.x : blockIdx.x - gblocks;
    const int v = bid * 8 + warp;
    if (gene) {
        if (v >= ng) return;
        float4 aA = agg_one<32>(rpGA, colGA, xGA, v, lane);
        float4 aB = agg_one<32>(rpGB, colGB, xGB, v, lane);
        if (lane < 8) {
            float nA = ndGA[v], nB = ndGB[v];
            float4 bAv = *(const float4*)(bGA + 4 * lane);
            float4 bBv = *(const float4*)(bGB + 4 * lane);
            float4 o;
            o.x = fmaxf(nA * aA.x + nB * aB.x + bAv.x + bBv.x, 0.f);
            o.y = fmaxf(nA * aA.y + nB * aB.y + bAv.y + bBv.y, 0.f);
            o.z = fmaxf(nA * aA.z + nB * aB.z + bAv.z + bBv.z, 0.f);
            o.w = fmaxf(nA * aA.w + nB * aB.w + bAv.w + bBv.w, 0.f);
            __half h0 = __float2half_rn(o.x), h1 = __float2half_rn(o.y);
            __half h2 = __float2half_rn(o.z), h3 = __float2half_rn(o.w);
            __half l0 = __float2half_rn(o.x - __half2float(h0));
            __half l1 = __float2half_rn(o.y - __half2float(h1));
            __half l2 = __float2half_rn(o.z - __half2float(h2));
            __half l3 = __float2half_rn(o.w - __half2float(h3));
            __half2 ph0 = __halves2half2(h0, h1), ph1 = __halves2half2(h2, h3);
            __half2 pl0 = __halves2half2(l0, l1), pl1 = __halves2half2(l2, l3);
            uint2 sh, sl;
            sh.x = *reinterpret_cast<uint32_t*>(&ph0); sh.y = *reinterpret_cast<uint32_t*>(&ph1);
            sl.x = *reinterpret_cast<uint32_t*>(&pl0); sl.y = *reinterpret_cast<uint32_t*>(&pl1);
            *(uint2*)(outAh + (size_t)v * 32 + 4 * lane) = sh;
            *(uint2*)(outAl + (size_t)v * 32 + 4 * lane) = sl;
        }
    } else {
        if (v >= nd) return;
        // every lane holds valid dims for d = lane & 7 after agg_one's full reduce
        float4 aA = agg_one<32>(rpDA, colDA, xDA, v, lane);
        float4 aB = agg_one<32>(rpDB, colDB, xDB, v, lane);
        const int d8 = lane & 7;
        float nA = ndDA[v], nB = ndDB[v];
        float4 bAv = *(const float4*)(bDA + 4 * d8);
        float4 bBv = *(const float4*)(bDB + 4 * d8);
        float4 o;
        o.x = fmaxf(nA * aA.x + nB * aB.x + bAv.x + bBv.x, 0.f);
        o.y = fmaxf(nA * aA.y + nB * aB.y + bAv.y + bBv.y, 0.f);
        o.z = fmaxf(nA * aA.z + nB * aB.z + bAv.z + bBv.z, 0.f);
        o.w = fmaxf(nA * aA.w + nB * aB.w + bAv.w + bBv.w, 0.f);
        // fused y = hd2_row @ Wout : y[lane] = sum_k o_k * Wout[k*32+lane]
        float y = 0.f;
        #pragma unroll
        for (int k = 0; k < 32; k++) {
            float comp = ((k & 3) == 0) ? o.x : ((k & 3) == 1) ? o.y : ((k & 3) == 2) ? o.z : o.w;
            float ok = __shfl_sync(0xFFFFFFFFu, comp, k >> 2);
            y = fmaf(ok, __ldg(Wout + (size_t)k * 32 + lane), y);
        }
        __half h = __float2half_rn(y);
        __half l = __float2half_rn(y - __half2float(h));
        outBh[(size_t)v * 32 + lane] = h;
        outBl[(size_t)v * 32 + lane] = l;
    }
}

// -------- split-fp16 tensor-core GEMM: C = (Ah+Al) @ (Bh+Bl)^T, fp32 accumulate --------
__global__ __launch_bounds__(256) void k_outgemm_mma(
    const __half* __restrict__ Ah, const __half* __restrict__ Al,
    const __half* __restrict__ Bh, const __half* __restrict__ Bl,
    float* __restrict__ C, int M, int N)
{
    __shared__ float cs[128][68];
    const int warp = threadIdx.x >> 5, lane = threadIdx.x & 31;
    const int wm = warp >> 2;
    const int wn = warp & 3;
    const int mb = blockIdx.y * 128;
    const int nb = blockIdx.x * 64;
    const int m0 = mb + wm * 64;
    const int n0 = nb + wn * 16;
    const int g = lane >> 2;
    const int t = lane & 3;

    float acc[4][2][4];
    #pragma unroll
    for (int mt = 0; mt < 4; mt++)
        #pragma unroll
        for (int nt = 0; nt < 2; nt++)
            #pragma unroll
            for (int q = 0; q < 4; q++) acc[mt][nt][q] = 0.f;

    #pragma unroll
    for (int kt = 0; kt < 2; kt++) {
        const int kb = kt * 16;
        uint32_t afh[4][4], afl[4][4];
        #pragma unroll
        for (int mt = 0; mt < 4; mt++) {
            int r0 = m0 + mt * 16 + g;
            int r1 = r0 + 8;
            afh[mt][0] = (r0 < M) ? *(const uint32_t*)(Ah + (size_t)r0 * 32 + kb + 2 * t) : 0u;
            afh[mt][1] = (r1 < M) ? *(const uint32_t*)(Ah + (size_t)r1 * 32 + kb + 2 * t) : 0u;
            afh[mt][2] = (r0 < M) ? *(const uint32_t*)(Ah + (size_t)r0 * 32 + kb + 8 + 2 * t) : 0u;
            afh[mt][3] = (r1 < M) ? *(const uint32_t*)(Ah + (size_t)r1 * 32 + kb + 8 + 2 * t) : 0u;
            afl[mt][0] = (r0 < M) ? *(const uint32_t*)(Al + (size_t)r0 * 32 + kb + 2 * t) : 0u;
            afl[mt][1] = (r1 < M) ? *(const uint32_t*)(Al + (size_t)r1 * 32 + kb + 2 * t) : 0u;
            afl[mt][2] = (r0 < M) ? *(const uint32_t*)(Al + (size_t)r0 * 32 + kb + 8 + 2 * t) : 0u;
            afl[mt][3] = (r1 < M) ? *(const uint32_t*)(Al + (size_t)r1 * 32 + kb + 8 + 2 * t) : 0u;
        }
        #pragma unroll
        for (int nt = 0; nt < 2; nt++) {
            int c = n0 + nt * 8 + g;
            uint32_t bh0 = (c < N) ? *(const uint32_t*)(Bh + (size_t)c * 32 + kb + 2 * t) : 0u;
            uint32_t bh1 = (c < N) ? *(const uint32_t*)(Bh + (size_t)c * 32 + kb + 8 + 2 * t) : 0u;
            uint32_t bl0 = (c < N) ? *(const uint32_t*)(Bl + (size_t)c * 32 + kb + 2 * t) : 0u;
            uint32_t bl1 = (c < N) ? *(const uint32_t*)(Bl + (size_t)c * 32 + kb + 8 + 2 * t) : 0u;
            #pragma unroll
            for (int mt = 0; mt < 4; mt++) {
                asm volatile(
                    "mma.sync.aligned.m16n8k16.row.col.f32.f16.f16.f32 "
                    "{%0,%1,%2,%3}, {%4,%5,%6,%7}, {%8,%9}, {%0,%1,%2,%3};"
                    : "+f"(acc[mt][nt][0]), "+f"(acc[mt][nt][1]),
                      "+f"(acc[mt][nt][2]), "+f"(acc[mt][nt][3])
                    : "r"(afh[mt][0]), "r"(afh[mt][1]), "r"(afh[mt][2]), "r"(afh[mt][3]),
                      "r"(bh0), "r"(bh1));
                asm volatile(
                    "mma.sync.aligned.m16n8k16.row.col.f32.f16.f16.f32 "
                    "{%0,%1,%2,%3}, {%4,%5,%6,%7}, {%8,%9}, {%0,%1,%2,%3};"
                    : "+f"(acc[mt][nt][0]), "+f"(acc[mt][nt][1]),
                      "+f"(acc[mt][nt][2]), "+f"(acc[mt][nt][3])
                    : "r"(afl[mt][0]), "r"(afl[mt][1]), "r"(afl[mt][2]), "r"(afl[mt][3]),
                      "r"(bh0), "r"(bh1));
                asm volatile(
                    "mma.sync.aligned.m16n8k16.row.col.f32.f16.f16.f32 "
                    "{%0,%1,%2,%3}, {%4,%5,%6,%7}, {%8,%9}, {%0,%1,%2,%3};"
                    : "+f"(acc[mt][nt][0]), "+f"(acc[mt][nt][1]),
                      "+f"(acc[mt][nt][2]), "+f"(acc[mt][nt][3])
                    : "r"(afh[mt][0]), "r"(afh[mt][1]), "r"(afh[mt][2]), "r"(afh[mt][3]),
                      "r"(bl0), "r"(bl1));
            }
        }
    }

    #pragma unroll
    for (int mt = 0; mt < 4; mt++) {
        int rr = wm * 64 + mt * 16 + g;
        #pragma unroll
        for (int nt = 0; nt < 2; nt++) {
            int cc = wn * 16 + nt * 8 + 2 * t;
            cs[rr][cc]         = acc[mt][nt][0];
            cs[rr][cc + 1]     = acc[mt][nt][1];
            cs[rr + 8][cc]     = acc[mt][nt][2];
            cs[rr + 8][cc + 1] = acc[mt][nt][3];
        }
    }
    __syncthreads();
    for (int i = threadIdx.x; i < 128 * 16; i += 256) {
        int row = i >> 4, c4 = (i & 15) << 2;
        int m = mb + row, n = nb + c4;
        if (m >= M) continue;
        if (n + 3 < N) {
            *(float4*)(C + (size_t)m * N + n) =
                make_float4(cs[row][c4], cs[row][c4 + 1], cs[row][c4 + 2], cs[row][c4 + 3]);
        } else {
            for (int q = 0; q < 4; q++)
                if (n + q < N) C[(size_t)m * N + n + q] = cs[row][c4 + q];
        }
    }
}

// ---------------- launch ----------------
#define SYMP(var, T, sym) do { void* _p; cudaGetSymbolAddress(&_p, sym); var = (T*)_p; } while (0)

extern "C" void kernel_launch(void* const* d_in, const int* in_sizes, int n_in,
                              void* d_out, int out_size)
{
    const float* feat_g = (const float*)d_in[0];
    const float* feat_d = (const float*)d_in[1];
    const int* gg_src = (const int*)d_in[2];
    const int* gg_dst = (const int*)d_in[3];
    const int* gd_src = (const int*)d_in[4];
    const int* gd_dst = (const int*)d_in[5];
    const int* dd_src = (const int*)d_in[6];
    const int* dd_dst = (const int*)d_in[7];
    const float* Wg   = (const float*)d_in[8];
    const float* Wd   = (const float*)d_in[9];
    const float* W1   = (const float*)d_in[10];
    const float* b1   = (const float*)d_in[11];
    const float* W2   = (const float*)d_in[12];
    const float* b2   = (const float*)d_in[13];
    const float* Wout = (const float*)d_in[14];
    const int n_gg = in_sizes[2], n_gd = in_sizes[4], n_dd = in_sizes[6];

    int *rp_gg, *rp_dg, *rp_gd, *rp_dd;
    int *col_gg, *col_dg, *col_gd, *col_dd;
    float *rs_gg_src, *rs_gg_dst, *rs_gd_src, *rs_gd_dst, *rs_dd_src, *rs_dd_dst;
    float *hg, *hd, *og, *od;
    __half *xga, *xgb, *xda, *xdb, *ah, *al, *bh, *bl;
    SYMP(rp_gg, int, g_rp_gg); SYMP(rp_dg, int, g_rp_dg);
    SYMP(rp_gd, int, g_rp_gd); SYMP(rp_dd, int, g_rp_dd);
    SYMP(col_gg, int, g_col_gg); SYMP(col_dg, int, g_col_dg);
    SYMP(col_gd, int, g_col_gd); SYMP(col_dd, int, g_col_dd);
    SYMP(rs_gg_src, float, g_rs_gg_src); SYMP(rs_gg_dst, float, g_rs_gg_dst);
    SYMP(rs_gd_src, float, g_rs_gd_src); SYMP(rs_gd_dst, float, g_rs_gd_dst);
    SYMP(rs_dd_src, float, g_rs_dd_src); SYMP(rs_dd_dst, float, g_rs_dd_dst);
    SYMP(hg, float, g_hg); SYMP(hd, float, g_hd);
    SYMP(og, float, g_og); SYMP(od, float, g_od);
    SYMP(xga, __half, g_xga); SYMP(xgb, __half, g_xgb);
    SYMP(xda, __half, g_xda); SYMP(xdb, __half, g_xdb);
    SYMP(ah, __half, g_ah);
    al = (__half*)og;            // og free during layer-2 agg (consumed by layer-2 transform)
    bh = (__half*)hd;            // g_hd free at layer-2 agg (fp16 pair fits in its 1.28MB)
    bl = (__half*)hd + NDN * 32;

    const int histB = 1024, scatB = 1024;
    const int embG = (NGN + 31) / 32, embD = (NDN + 31) / 32;
    const int t2G = (NGN + 15) / 16, t2D = (NDN + 15) / 16;
    const int agG = (NGN + 7) / 8, agD = (NDN + 7) / 8;

    // A) zero counters
    k_zero_counts<<<(NGN + 255) / 256, 256>>>();
    // B) histogram  ||  embeddings (independent, one launch)
    k_hist_embed<<<histB + embG + embD, 256>>>(
        gg_src, gg_dst, gd_src, gd_dst, dd_src, dd_dst, n_gg, n_gd, n_dd, histB,
        feat_g, Wg, hg, NGN, feat_d, Wd, hd, NDN, embG);
    // C) scans + rsqrt
    k_setup2<<<4 + (NGN + 1023) / 1024, 1024>>>();
    // D) CSR fill  ||  layer-1 dual transform (both depend only on B + C)
    k_scatter_t2<<<scatB + t2G + t2D, 256>>>(
        gg_src, gg_dst, gd_src, gd_dst, dd_src, dd_dst, n_gg, n_gd, n_dd, scatB,
        hg, rs_gg_src, W1 + 0 * 64 * 64, rs_gd_src, W1 + 1 * 64 * 64, xga, xgb, NGN,
        hd, rs_gd_dst, W1 + 2 * 64 * 64, rs_dd_src, W1 + 3 * 64 * 64, xda, xdb, NDN, t2G);
    // E) layer-1 aggregation (both node types)
    k_agg_pair64<<<agG + agD, 256>>>(
        rp_gg, col_gg, xga, rs_gg_dst, rp_dg, col_dg, xda, rs_gd_src,
        b1 + 0 * 64, b1 + 2 * 64, og, NGN,
        rp_gd, col_gd, xgb, rs_gd_dst, rp_dd, col_dd, xdb, rs_dd_dst,
        b1 + 1 * 64, b1 + 3 * 64, od, NDN, agG);
    // F) layer-2 dual transform
    k_t2_pair32<<<t2G + t2D, 256>>>(
        og, rs_gg_src, W2 + 0 * 32 * 64, rs_gd_src, W2 + 1 * 32 * 64, xga, xgb, NGN,
        od, rs_gd_dst, W2 + 2 * 32 * 64, rs_dd_src, W2 + 3 * 32 * 64, xda, xdb, NDN, t2G);
    // G) layer-2 aggregation; gene -> (Ah,Al), disease -> fused @Wout -> (Bh,Bl)
    k_agg_pair32_final<<<agG + agD, 256>>>(
        rp_gg, col_gg, xga, rs_gg_dst, rp_dg, col_dg, xda, rs_gd_src,
        b2 + 0 * 32, b2 + 2 * 32, ah, al, NGN,
        rp_gd, col_gd, xgb, rs_gd_dst, rp_dd, col_dd, xdb, rs_dd_dst,
        b2 + 1 * 32, b2 + 3 * 32, Wout, bh, bl, NDN, agG);
    // H) out = (Ah+Al) @ (Bh+Bl)^T via split-fp16 tensor cores
    dim3 grid((NDN + 63) / 64, (NGN + 127) / 128);
    k_outgemm_mma<<<grid, 256>>>(ah, al, bh, bl, (float*)d_out, NGN, NDN);
}

// round 11
// speedup vs baseline: 1.1402x; 1.1402x over previous
#include <cuda_runtime.h>
#include <cuda_fp16.h>
#include <math.h>
#include <stdint.h>

#define NGN 12331
#define NDN 5000
#define EGG 1000000
#define EGD 400000
#define EDD 100000

// ---------------- scratch (device globals; no allocation allowed) ----------------
__device__ int g_cnt_gg_src[NGN], g_cnt_gg_dst[NGN], g_cnt_gd_src[NGN];
__device__ int g_cnt_gd_dst[NDN], g_cnt_dd_src[NDN], g_cnt_dd_dst[NDN];
__device__ int g_rp_gg[NGN + 1], g_rp_dg[NGN + 1], g_rp_gd[NDN + 1], g_rp_dd[NDN + 1];
__device__ int g_fill_gg[NGN], g_fill_dg[NGN], g_fill_gd[NDN], g_fill_dd[NDN];
__device__ int g_col_gg[EGG], g_col_dg[EGD], g_col_gd[EGD], g_col_dd[EDD];
__device__ float g_rs_gg_src[NGN], g_rs_gg_dst[NGN], g_rs_gd_src[NGN];
__device__ float g_rs_gd_dst[NDN], g_rs_dd_src[NDN], g_rs_dd_dst[NDN];
__device__ __align__(256) float g_hg[NGN * 64];
__device__ __align__(256) float g_hd[NDN * 64];   // reused late as bh/bl (fp16 pair, 640KB < 1.28MB)
__device__ __align__(256) __half g_xga[NGN * 64], g_xgb[NGN * 64];
__device__ __align__(256) __half g_xda[NDN * 64], g_xdb[NDN * 64];
__device__ __align__(256) __half g_ah[NGN * 32];
__device__ __align__(256) float g_og[NGN * 64];
__device__ __align__(256) float g_od[NDN * 64];

// ---------------- setup ----------------
__global__ void k_zero_counts() {
    int i = blockIdx.x * blockDim.x + threadIdx.x;
    if (i < NGN) { g_cnt_gg_src[i] = 0; g_cnt_gg_dst[i] = 0; g_cnt_gd_src[i] = 0; }
    if (i < NDN) { g_cnt_gd_dst[i] = 0; g_cnt_dd_src[i] = 0; g_cnt_dd_dst[i] = 0; }
}

__global__ void k_hist_all(const int* __restrict__ gg_s, const int* __restrict__ gg_d,
                           const int* __restrict__ gd_s, const int* __restrict__ gd_d,
                           const int* __restrict__ dd_s, const int* __restrict__ dd_d,
                           int ngg, int ngd, int ndd) {
    const int total = ngg + ngd + ndd;
    for (int i = blockIdx.x * blockDim.x + threadIdx.x; i < total; i += gridDim.x * blockDim.x) {
        if (i < ngg) {
            atomicAdd(&g_cnt_gg_src[gg_s[i]], 1);
            atomicAdd(&g_cnt_gg_dst[gg_d[i]], 1);
        } else if (i < ngg + ngd) {
            int j = i - ngg;
            atomicAdd(&g_cnt_gd_src[gd_s[j]], 1);
            atomicAdd(&g_cnt_gd_dst[gd_d[j]], 1);
        } else {
            int j = i - ngg - ngd;
            atomicAdd(&g_cnt_dd_src[dd_s[j]], 1);
            atomicAdd(&g_cnt_dd_dst[dd_d[j]], 1);
        }
    }
}

// blocks 0..3: 4 single-block exclusive scans; blocks 4+: rsqrt of all degree arrays
__global__ void k_setup2() {
    __shared__ int warp_tot[32];
    if (blockIdx.x >= 4) {
        int i = (blockIdx.x - 4) * 1024 + threadIdx.x;
        if (i < NGN) {
            g_rs_gg_src[i] = rsqrtf((float)max(g_cnt_gg_src[i], 1));
            g_rs_gg_dst[i] = rsqrtf((float)max(g_cnt_gg_dst[i], 1));
            g_rs_gd_src[i] = rsqrtf((float)max(g_cnt_gd_src[i], 1));
        }
        if (i < NDN) {
            g_rs_gd_dst[i] = rsqrtf((float)max(g_cnt_gd_dst[i], 1));
            g_rs_dd_src[i] = rsqrtf((float)max(g_cnt_dd_src[i], 1));
            g_rs_dd_dst[i] = rsqrtf((float)max(g_cnt_dd_dst[i], 1));
        }
        return;
    }
    const int* cnt; int* rp; int* fill; int n;
    if (blockIdx.x == 0)      { cnt = g_cnt_gg_dst; rp = g_rp_gg; fill = g_fill_gg; n = NGN; }
    else if (blockIdx.x == 1) { cnt = g_cnt_gd_src; rp = g_rp_dg; fill = g_fill_dg; n = NGN; }
    else if (blockIdx.x == 2) { cnt = g_cnt_gd_dst; rp = g_rp_gd; fill = g_fill_gd; n = NDN; }
    else                      { cnt = g_cnt_dd_dst; rp = g_rp_dd; fill = g_fill_dd; n = NDN; }
    const int t = threadIdx.x;
    const int lane = t & 31, w = t >> 5;
    const int C = (n + 1023) / 1024;
    int lo = t * C, hi = min((t + 1) * C, n);
    int s = 0;
    for (int i = lo; i < hi; i++) s += cnt[i];
    int v = s;
    #pragma unroll
    for (int o = 1; o < 32; o <<= 1) {
        int u = __shfl_up_sync(0xFFFFFFFFu, v, o);
        if (lane >= o) v += u;
    }
    if (lane == 31) warp_tot[w] = v;
    __syncthreads();
    if (w == 0) {
        int x = warp_tot[lane];
        #pragma unroll
        for (int o = 1; o < 32; o <<= 1) {
            int u = __shfl_up_sync(0xFFFFFFFFu, x, o);
            if (lane >= o) x += u;
        }
        warp_tot[lane] = x;
    }
    __syncthreads();
    int run = v - s + (w > 0 ? warp_tot[w - 1] : 0);  // exclusive prefix
    for (int i = lo; i < hi; i++) { int c = cnt[i]; rp[i] = run; fill[i] = run; run += c; }
    if (t == 1023) rp[n] = run;
}

__global__ void k_scatter_all(const int* __restrict__ gg_s, const int* __restrict__ gg_d,
                              const int* __restrict__ gd_s, const int* __restrict__ gd_d,
                              const int* __restrict__ dd_s, const int* __restrict__ dd_d,
                              int ngg, int ngd, int ndd) {
    const int total = ngg + ngd + ndd;
    for (int i = blockIdx.x * blockDim.x + threadIdx.x; i < total; i += gridDim.x * blockDim.x) {
        if (i < ngg) {
            int r = gg_d[i];
            int p = atomicAdd(&g_fill_gg[r], 1);
            g_col_gg[p] = gg_s[i];
        } else if (i < ngg + ngd) {
            int j = i - ngg;
            int s = gd_s[j], d = gd_d[j];
            int p = atomicAdd(&g_fill_dg[s], 1);  // reversed: disease->gene
            g_col_dg[p] = d;
            int q = atomicAdd(&g_fill_gd[d], 1);  // gene->disease
            g_col_gd[q] = s;
        } else {
            int j = i - ngg - ngd;
            int r = dd_d[j];
            int p = atomicAdd(&g_fill_dd[r], 1);
            g_col_dd[p] = dd_s[j];
        }
    }
}

// ---------------- embeddings (both node types in one launch): H = F @ W.T ----------------
__global__ __launch_bounds__(256) void k_embed_pair(
    const float* __restrict__ Fg, const float* __restrict__ Wg, float* __restrict__ Hg, int ng,
    const float* __restrict__ Fd, const float* __restrict__ Wd, float* __restrict__ Hd, int nd,
    int gblocks)
{
    constexpr int RPW = 4;
    __shared__ float Wt[64][64];
    __shared__ float hs[8][RPW][64];
    const float *F, *W; float* H; int n, bid;
    if (blockIdx.x < gblocks) { F = Fg; W = Wg; H = Hg; n = ng; bid = blockIdx.x; }
    else                      { F = Fd; W = Wd; H = Hd; n = nd; bid = blockIdx.x - gblocks; }
    const int warp = threadIdx.x >> 5, lane = threadIdx.x & 31;
    const int base = bid * 8 * RPW;
    float acc[RPW][2];
    #pragma unroll
    for (int i = 0; i < RPW; i++) { acc[i][0] = 0.f; acc[i][1] = 0.f; }
    for (int c = 0; c < 8; c++) {
        __syncthreads();
        for (int i = threadIdx.x; i < 64 * 64; i += 256) {
            int k = i >> 6, o = i & 63;
            Wt[k][o] = W[(size_t)o * 512 + c * 64 + k];
        }
        #pragma unroll
        for (int rr = 0; rr < RPW; rr++) {
            int r = base + warp * RPW + rr;
            if (r < n) {
                hs[warp][rr][lane]      = F[(size_t)r * 512 + c * 64 + lane];
                hs[warp][rr][lane + 32] = F[(size_t)r * 512 + c * 64 + lane + 32];
            }
        }
        __syncthreads();
        #pragma unroll
        for (int k = 0; k < 64; k++) {
            float w0 = Wt[k][lane], w1 = Wt[k][lane + 32];
            #pragma unroll
            for (int rr = 0; rr < RPW; rr++) {
                float h = hs[warp][rr][k];
                acc[rr][0] = fmaf(h, w0, acc[rr][0]);
                acc[rr][1] = fmaf(h, w1, acc[rr][1]);
            }
        }
    }
    #pragma unroll
    for (int rr = 0; rr < RPW; rr++) {
        int r = base + warp * RPW + rr;
        if (r < n) {
            H[(size_t)r * 64 + lane]      = acc[rr][0];
            H[(size_t)r * 64 + lane + 32] = acc[rr][1];
        }
    }
}

// -------- fused dual-relation transform (DOUT=64), both node types, fp16 out --------
__global__ __launch_bounds__(256) void k_t2_pair64(
    const float* __restrict__ Hg,
    const float* __restrict__ sGA, const float* __restrict__ WGA,
    const float* __restrict__ sGB, const float* __restrict__ WGB,
    __half* __restrict__ XGA, __half* __restrict__ XGB, int ng,
    const float* __restrict__ Hd,
    const float* __restrict__ sDA, const float* __restrict__ WDA,
    const float* __restrict__ sDB, const float* __restrict__ WDB,
    __half* __restrict__ XDA, __half* __restrict__ XDB, int nd,
    int gblocks)
{
    constexpr int RPW = 2;
    __shared__ float WtA[64][64];
    __shared__ float WtB[64][64];
    __shared__ float hs[8][RPW][64];
    const float *H, *scA, *WA, *scB, *WB; __half *XA, *XB; int n, bid;
    if (blockIdx.x < gblocks) {
        H = Hg; scA = sGA; WA = WGA; scB = sGB; WB = WGB; XA = XGA; XB = XGB;
        n = ng; bid = blockIdx.x;
    } else {
        H = Hd; scA = sDA; WA = WDA; scB = sDB; WB = WDB; XA = XDA; XB = XDB;
        n = nd; bid = blockIdx.x - gblocks;
    }
    const int warp = threadIdx.x >> 5, lane = threadIdx.x & 31;
    const int base = bid * 8 * RPW;
    for (int i = threadIdx.x; i < 64 * 64; i += 256) {
        int k = i >> 6, o = i & 63;
        WtA[k][o] = WA[(size_t)o * 64 + k];
        WtB[k][o] = WB[(size_t)o * 64 + k];
    }
    #pragma unroll
    for (int rr = 0; rr < RPW; rr++) {
        int r = base + warp * RPW + rr;
        if (r < n) {
            hs[warp][rr][lane]      = H[(size_t)r * 64 + lane];
            hs[warp][rr][lane + 32] = H[(size_t)r * 64 + lane + 32];
        }
    }
    __syncthreads();
    float aA[RPW][2], aB[RPW][2];
    #pragma unroll
    for (int i = 0; i < RPW; i++) { aA[i][0] = aA[i][1] = 0.f; aB[i][0] = aB[i][1] = 0.f; }
    #pragma unroll
    for (int k = 0; k < 64; k++) {
        float wa0 = WtA[k][lane], wb0 = WtB[k][lane];
        float wa1 = WtA[k][lane + 32], wb1 = WtB[k][lane + 32];
        #pragma unroll
        for (int rr = 0; rr < RPW; rr++) {
            float h = hs[warp][rr][k];
            aA[rr][0] = fmaf(h, wa0, aA[rr][0]);
            aB[rr][0] = fmaf(h, wb0, aB[rr][0]);
            aA[rr][1] = fmaf(h, wa1, aA[rr][1]);
            aB[rr][1] = fmaf(h, wb1, aB[rr][1]);
        }
    }
    #pragma unroll
    for (int rr = 0; rr < RPW; rr++) {
        int r = base + warp * RPW + rr;
        if (r < n) {
            float sA = scA[r], sB = scB[r];
            XA[(size_t)r * 64 + lane]      = __float2half_rn(aA[rr][0] * sA);
            XB[(size_t)r * 64 + lane]      = __float2half_rn(aB[rr][0] * sB);
            XA[(size_t)r * 64 + lane + 32] = __float2half_rn(aA[rr][1] * sA);
            XB[(size_t)r * 64 + lane + 32] = __float2half_rn(aB[rr][1] * sB);
        }
    }
}

// -------- layer-2 dual transform (DOUT=32), both node types --------
__global__ __launch_bounds__(256) void k_t2_pair32(
    const float* __restrict__ Hg,
    const float* __restrict__ sGA, const float* __restrict__ WGA,
    const float* __restrict__ sGB, const float* __restrict__ WGB,
    __half* __restrict__ XGA, __half* __restrict__ XGB, int ng,
    const float* __restrict__ Hd,
    const float* __restrict__ sDA, const float* __restrict__ WDA,
    const float* __restrict__ sDB, const float* __restrict__ WDB,
    __half* __restrict__ XDA, __half* __restrict__ XDB, int nd,
    int gblocks)
{
    constexpr int RPW = 2;
    __shared__ float WtA[64][32];
    __shared__ float WtB[64][32];
    __shared__ float hs[8][RPW][64];
    const float *H, *scA, *WA, *scB, *WB; __half *XA, *XB; int n, bid;
    if (blockIdx.x < gblocks) {
        H = Hg; scA = sGA; WA = WGA; scB = sGB; WB = WGB; XA = XGA; XB = XGB;
        n = ng; bid = blockIdx.x;
    } else {
        H = Hd; scA = sDA; WA = WDA; scB = sDB; WB = WDB; XA = XDA; XB = XDB;
        n = nd; bid = blockIdx.x - gblocks;
    }
    const int warp = threadIdx.x >> 5, lane = threadIdx.x & 31;
    const int base = bid * 8 * RPW;
    for (int i = threadIdx.x; i < 64 * 32; i += 256) {
        int k = i >> 5, o = i & 31;
        WtA[k][o] = WA[(size_t)o * 64 + k];
        WtB[k][o] = WB[(size_t)o * 64 + k];
    }
    #pragma unroll
    for (int rr = 0; rr < RPW; rr++) {
        int r = base + warp * RPW + rr;
        if (r < n) {
            hs[warp][rr][lane]      = H[(size_t)r * 64 + lane];
            hs[warp][rr][lane + 32] = H[(size_t)r * 64 + lane + 32];
        }
    }
    __syncthreads();
    float aA[RPW], aB[RPW];
    #pragma unroll
    for (int i = 0; i < RPW; i++) { aA[i] = 0.f; aB[i] = 0.f; }
    #pragma unroll
    for (int k = 0; k < 64; k++) {
        float wa = WtA[k][lane], wb = WtB[k][lane];
        #pragma unroll
        for (int rr = 0; rr < RPW; rr++) {
            float h = hs[warp][rr][k];
            aA[rr] = fmaf(h, wa, aA[rr]);
            aB[rr] = fmaf(h, wb, aB[rr]);
        }
    }
    #pragma unroll
    for (int rr = 0; rr < RPW; rr++) {
        int r = base + warp * RPW + rr;
        if (r < n) {
            XA[(size_t)r * 32 + lane] = __float2half_rn(aA[rr] * scA[r]);
            XB[(size_t)r * 32 + lane] = __float2half_rn(aB[rr] * scB[r]);
        }
    }
}

// ------- vectorized CSR gather-sum: LDG.64, up to 8 outstanding loads/warp -------
// after the xor-reduce, EVERY lane holds the full sum for dims [4d..4d+3], d = lane % (DOUT/4)
template <int DOUT>
__device__ __forceinline__ float4 agg_one(const int* __restrict__ rp, const int* __restrict__ col,
                                          const __half* __restrict__ x, int v, int lane)
{
    constexpr int LPE = DOUT / 4;   // lanes per edge (16 for D64, 8 for D32)
    constexpr int EPW = 32 / LPE;   // edges per warp step (2 or 4)
    const int sub = lane / LPE;
    const int d = lane - sub * LPE;
    const __half* base = x + d * 4;
    float4 acc = make_float4(0.f, 0.f, 0.f, 0.f);
    int s = rp[v], e = rp[v + 1], j = s;
    for (; j + 4 * EPW <= e; j += 4 * EPW) {
        int u0 = col[j + sub];
        int u1 = col[j + EPW + sub];
        int u2 = col[j + 2 * EPW + sub];
        int u3 = col[j + 3 * EPW + sub];
        uint2 r0 = *(const uint2*)(base + (size_t)u0 * DOUT);
        uint2 r1 = *(const uint2*)(base + (size_t)u1 * DOUT);
        uint2 r2 = *(const uint2*)(base + (size_t)u2 * DOUT);
        uint2 r3 = *(const uint2*)(base + (size_t)u3 * DOUT);
        float2 a0 = __half22float2(*reinterpret_cast<__half2*>(&r0.x));
        float2 a1 = __half22float2(*reinterpret_cast<__half2*>(&r0.y));
        float2 b0 = __half22float2(*reinterpret_cast<__half2*>(&r1.x));
        float2 b1 = __half22float2(*reinterpret_cast<__half2*>(&r1.y));
        float2 c0 = __half22float2(*reinterpret_cast<__half2*>(&r2.x));
        float2 c1 = __half22float2(*reinterpret_cast<__half2*>(&r2.y));
        float2 d0 = __half22float2(*reinterpret_cast<__half2*>(&r3.x));
        float2 d1 = __half22float2(*reinterpret_cast<__half2*>(&r3.y));
        acc.x += (a0.x + b0.x) + (c0.x + d0.x);
        acc.y += (a0.y + b0.y) + (c0.y + d0.y);
        acc.z += (a1.x + b1.x) + (c1.x + d1.x);
        acc.w += (a1.y + b1.y) + (c1.y + d1.y);
    }
    for (; j + EPW <= e; j += EPW) {
        int u = col[j + sub];
        uint2 r0 = *(const uint2*)(base + (size_t)u * DOUT);
        float2 a0 = __half22float2(*reinterpret_cast<__half2*>(&r0.x));
        float2 a1 = __half22float2(*reinterpret_cast<__half2*>(&r0.y));
        acc.x += a0.x; acc.y += a0.y; acc.z += a1.x; acc.w += a1.y;
    }
    if (j + sub < e) {
        int u = col[j + sub];
        uint2 r0 = *(const uint2*)(base + (size_t)u * DOUT);
        float2 a0 = __half22float2(*reinterpret_cast<__half2*>(&r0.x));
        float2 a1 = __half22float2(*reinterpret_cast<__half2*>(&r0.y));
        acc.x += a0.x; acc.y += a0.y; acc.z += a1.x; acc.w += a1.y;
    }
    #pragma unroll
    for (int off = LPE; off < 32; off <<= 1) {
        acc.x += __shfl_xor_sync(0xFFFFFFFFu, acc.x, off);
        acc.y += __shfl_xor_sync(0xFFFFFFFFu, acc.y, off);
        acc.z += __shfl_xor_sync(0xFFFFFFFFu, acc.z, off);
        acc.w += __shfl_xor_sync(0xFFFFFFFFu, acc.w, off);
    }
    return acc;
}

// ------- layer-1 dual-relation aggregation, both node types, fp32 out -------
__global__ __launch_bounds__(256) void k_agg_pair64(
    const int* __restrict__ rpGA, const int* __restrict__ colGA,
    const __half* __restrict__ xGA, const float* __restrict__ ndGA,
    const int* __restrict__ rpGB, const int* __restrict__ colGB,
    const __half* __restrict__ xGB, const float* __restrict__ ndGB,
    const float* __restrict__ bGA, const float* __restrict__ bGB,
    float* __restrict__ outG, int ng,
    const int* __restrict__ rpDA, const int* __restrict__ colDA,
    const __half* __restrict__ xDA, const float* __restrict__ ndDA,
    const int* __restrict__ rpDB, const int* __restrict__ colDB,
    const __half* __restrict__ xDB, const float* __restrict__ ndDB,
    const float* __restrict__ bDA, const float* __restrict__ bDB,
    float* __restrict__ outD, int nd, int gblocks)
{
    const int warp = threadIdx.x >> 5, lane = threadIdx.x & 31;
    const bool gene = (int)blockIdx.x < gblocks;
    const int bid = gene ? blockIdx.x : blockIdx.x - gblocks;
    const int v = bid * 8 + warp;
    const int* rpA  = gene ? rpGA : rpDA;  const int* colA = gene ? colGA : colDA;
    const __half* xA = gene ? xGA : xDA;   const float* ndA = gene ? ndGA : ndDA;
    const int* rpB  = gene ? rpGB : rpDB;  const int* colB = gene ? colGB : colDB;
    const __half* xB = gene ? xGB : xDB;   const float* ndB = gene ? ndGB : ndDB;
    const float* bA = gene ? bGA : bDA;    const float* bB = gene ? bGB : bDB;
    float* out = gene ? outG : outD;
    const int n = gene ? ng : nd;
    if (v >= n) return;
    float4 aA = agg_one<64>(rpA, colA, xA, v, lane);
    float4 aB = agg_one<64>(rpB, colB, xB, v, lane);
    if (lane < 16) {
        float nA = ndA[v], nB = ndB[v];
        float4 bAv = *(const float4*)(bA + 4 * lane);
        float4 bBv = *(const float4*)(bB + 4 * lane);
        float4 o;
        o.x = fmaxf(nA * aA.x + nB * aB.x + bAv.x + bBv.x, 0.f);
        o.y = fmaxf(nA * aA.y + nB * aB.y + bAv.y + bBv.y, 0.f);
        o.z = fmaxf(nA * aA.z + nB * aB.z + bAv.z + bBv.z, 0.f);
        o.w = fmaxf(nA * aA.w + nB * aB.w + bAv.w + bBv.w, 0.f);
        *(float4*)(out + (size_t)v * 64 + 4 * lane) = o;
    }
}

// ------- layer-2 aggregation: gene -> split-fp16 (Ah,Al); disease -> fused @Wout -> (Bh,Bl) -------
__global__ __launch_bounds__(256) void k_agg_pair32_final(
    const int* __restrict__ rpGA, const int* __restrict__ colGA,
    const __half* __restrict__ xGA, const float* __restrict__ ndGA,
    const int* __restrict__ rpGB, const int* __restrict__ colGB,
    const __half* __restrict__ xGB, const float* __restrict__ ndGB,
    const float* __restrict__ bGA, const float* __restrict__ bGB,
    __half* __restrict__ outAh, __half* __restrict__ outAl, int ng,
    const int* __restrict__ rpDA, const int* __restrict__ colDA,
    const __half* __restrict__ xDA, const float* __restrict__ ndDA,
    const int* __restrict__ rpDB, const int* __restrict__ colDB,
    const __half* __restrict__ xDB, const float* __restrict__ ndDB,
    const float* __restrict__ bDA, const float* __restrict__ bDB,
    const float* __restrict__ Wout,
    __half* __restrict__ outBh, __half* __restrict__ outBl, int nd, int gblocks)
{
    const int warp = threadIdx.x >> 5, lane = threadIdx.x & 31;
    const bool gene = (int)blockIdx.x < gblocks;
    const int bid = gene ? blockIdx.x : blockIdx.x - gblocks;
    const int v = bid * 8 + warp;
    if (gene) {
        if (v >= ng) return;
        float4 aA = agg_one<32>(rpGA, colGA, xGA, v, lane);
        float4 aB = agg_one<32>(rpGB, colGB, xGB, v, lane);
        if (lane < 8) {
            float nA = ndGA[v], nB = ndGB[v];
            float4 bAv = *(const float4*)(bGA + 4 * lane);
            float4 bBv = *(const float4*)(bGB + 4 * lane);
            float4 o;
            o.x = fmaxf(nA * aA.x + nB * aB.x + bAv.x + bBv.x, 0.f);
            o.y = fmaxf(nA * aA.y + nB * aB.y + bAv.y + bBv.y, 0.f);
            o.z = fmaxf(nA * aA.z + nB * aB.z + bAv.z + bBv.z, 0.f);
            o.w = fmaxf(nA * aA.w + nB * aB.w + bAv.w + bBv.w, 0.f);
            __half h0 = __float2half_rn(o.x), h1 = __float2half_rn(o.y);
            __half h2 = __float2half_rn(o.z), h3 = __float2half_rn(o.w);
            __half l0 = __float2half_rn(o.x - __half2float(h0));
            __half l1 = __float2half_rn(o.y - __half2float(h1));
            __half l2 = __float2half_rn(o.z - __half2float(h2));
            __half l3 = __float2half_rn(o.w - __half2float(h3));
            __half2 ph0 = __halves2half2(h0, h1), ph1 = __halves2half2(h2, h3);
            __half2 pl0 = __halves2half2(l0, l1), pl1 = __halves2half2(l2, l3);
            uint2 sh, sl;
            sh.x = *reinterpret_cast<uint32_t*>(&ph0); sh.y = *reinterpret_cast<uint32_t*>(&ph1);
            sl.x = *reinterpret_cast<uint32_t*>(&pl0); sl.y = *reinterpret_cast<uint32_t*>(&pl1);
            *(uint2*)(outAh + (size_t)v * 32 + 4 * lane) = sh;
            *(uint2*)(outAl + (size_t)v * 32 + 4 * lane) = sl;
        }
    } else {
        if (v >= nd) return;
        // every lane holds valid dims for d = lane & 7 after agg_one's full reduce
        float4 aA = agg_one<32>(rpDA, colDA, xDA, v, lane);
        float4 aB = agg_one<32>(rpDB, colDB, xDB, v, lane);
        const int d8 = lane & 7;
        float nA = ndDA[v], nB = ndDB[v];
        float4 bAv = *(const float4*)(bDA + 4 * d8);
        float4 bBv = *(const float4*)(bDB + 4 * d8);
        float4 o;
        o.x = fmaxf(nA * aA.x + nB * aB.x + bAv.x + bBv.x, 0.f);
        o.y = fmaxf(nA * aA.y + nB * aB.y + bAv.y + bBv.y, 0.f);
        o.z = fmaxf(nA * aA.z + nB * aB.z + bAv.z + bBv.z, 0.f);
        o.w = fmaxf(nA * aA.w + nB * aB.w + bAv.w + bBv.w, 0.f);
        // fused y = hd2_row @ Wout : y[lane] = sum_k o_k * Wout[k*32+lane]
        float y = 0.f;
        #pragma unroll
        for (int k = 0; k < 32; k++) {
            float comp = ((k & 3) == 0) ? o.x : ((k & 3) == 1) ? o.y : ((k & 3) == 2) ? o.z : o.w;
            float ok = __shfl_sync(0xFFFFFFFFu, comp, k >> 2);
            y = fmaf(ok, __ldg(Wout + (size_t)k * 32 + lane), y);
        }
        __half h = __float2half_rn(y);
        __half l = __float2half_rn(y - __half2float(h));
        outBh[(size_t)v * 32 + lane] = h;
        outBl[(size_t)v * 32 + lane] = l;
    }
}

// -------- split-fp16 tensor-core GEMM: C = (Ah+Al) @ (Bh+Bl)^T, fp32 accumulate --------
__global__ __launch_bounds__(256) void k_outgemm_mma(
    const __half* __restrict__ Ah, const __half* __restrict__ Al,
    const __half* __restrict__ Bh, const __half* __restrict__ Bl,
    float* __restrict__ C, int M, int N)
{
    __shared__ float cs[128][68];
    const int warp = threadIdx.x >> 5, lane = threadIdx.x & 31;
    const int wm = warp >> 2;
    const int wn = warp & 3;
    const int mb = blockIdx.y * 128;
    const int nb = blockIdx.x * 64;
    const int m0 = mb + wm * 64;
    const int n0 = nb + wn * 16;
    const int g = lane >> 2;
    const int t = lane & 3;

    float acc[4][2][4];
    #pragma unroll
    for (int mt = 0; mt < 4; mt++)
        #pragma unroll
        for (int nt = 0; nt < 2; nt++)
            #pragma unroll
            for (int q = 0; q < 4; q++) acc[mt][nt][q] = 0.f;

    #pragma unroll
    for (int kt = 0; kt < 2; kt++) {
        const int kb = kt * 16;
        uint32_t afh[4][4], afl[4][4];
        #pragma unroll
        for (int mt = 0; mt < 4; mt++) {
            int r0 = m0 + mt * 16 + g;
            int r1 = r0 + 8;
            afh[mt][0] = (r0 < M) ? *(const uint32_t*)(Ah + (size_t)r0 * 32 + kb + 2 * t) : 0u;
            afh[mt][1] = (r1 < M) ? *(const uint32_t*)(Ah + (size_t)r1 * 32 + kb + 2 * t) : 0u;
            afh[mt][2] = (r0 < M) ? *(const uint32_t*)(Ah + (size_t)r0 * 32 + kb + 8 + 2 * t) : 0u;
            afh[mt][3] = (r1 < M) ? *(const uint32_t*)(Ah + (size_t)r1 * 32 + kb + 8 + 2 * t) : 0u;
            afl[mt][0] = (r0 < M) ? *(const uint32_t*)(Al + (size_t)r0 * 32 + kb + 2 * t) : 0u;
            afl[mt][1] = (r1 < M) ? *(const uint32_t*)(Al + (size_t)r1 * 32 + kb + 2 * t) : 0u;
            afl[mt][2] = (r0 < M) ? *(const uint32_t*)(Al + (size_t)r0 * 32 + kb + 8 + 2 * t) : 0u;
            afl[mt][3] = (r1 < M) ? *(const uint32_t*)(Al + (size_t)r1 * 32 + kb + 8 + 2 * t) : 0u;
        }
        #pragma unroll
        for (int nt = 0; nt < 2; nt++) {
            int c = n0 + nt * 8 + g;
            uint32_t bh0 = (c < N) ? *(const uint32_t*)(Bh + (size_t)c * 32 + kb + 2 * t) : 0u;
            uint32_t bh1 = (c < N) ? *(const uint32_t*)(Bh + (size_t)c * 32 + kb + 8 + 2 * t) : 0u;
            uint32_t bl0 = (c < N) ? *(const uint32_t*)(Bl + (size_t)c * 32 + kb + 2 * t) : 0u;
            uint32_t bl1 = (c < N) ? *(const uint32_t*)(Bl + (size_t)c * 32 + kb + 8 + 2 * t) : 0u;
            #pragma unroll
            for (int mt = 0; mt < 4; mt++) {
                asm volatile(
                    "mma.sync.aligned.m16n8k16.row.col.f32.f16.f16.f32 "
                    "{%0,%1,%2,%3}, {%4,%5,%6,%7}, {%8,%9}, {%0,%1,%2,%3};"
                    : "+f"(acc[mt][nt][0]), "+f"(acc[mt][nt][1]),
                      "+f"(acc[mt][nt][2]), "+f"(acc[mt][nt][3])
                    : "r"(afh[mt][0]), "r"(afh[mt][1]), "r"(afh[mt][2]), "r"(afh[mt][3]),
                      "r"(bh0), "r"(bh1));
                asm volatile(
                    "mma.sync.aligned.m16n8k16.row.col.f32.f16.f16.f32 "
                    "{%0,%1,%2,%3}, {%4,%5,%6,%7}, {%8,%9}, {%0,%1,%2,%3};"
                    : "+f"(acc[mt][nt][0]), "+f"(acc[mt][nt][1]),
                      "+f"(acc[mt][nt][2]), "+f"(acc[mt][nt][3])
                    : "r"(afl[mt][0]), "r"(afl[mt][1]), "r"(afl[mt][2]), "r"(afl[mt][3]),
                      "r"(bh0), "r"(bh1));
                asm volatile(
                    "mma.sync.aligned.m16n8k16.row.col.f32.f16.f16.f32 "
                    "{%0,%1,%2,%3}, {%4,%5,%6,%7}, {%8,%9}, {%0,%1,%2,%3};"
                    : "+f"(acc[mt][nt][0]), "+f"(acc[mt][nt][1]),
                      "+f"(acc[mt][nt][2]), "+f"(acc[mt][nt][3])
                    : "r"(afh[mt][0]), "r"(afh[mt][1]), "r"(afh[mt][2]), "r"(afh[mt][3]),
                      "r"(bl0), "r"(bl1));
            }
        }
    }

    #pragma unroll
    for (int mt = 0; mt < 4; mt++) {
        int rr = wm * 64 + mt * 16 + g;
        #pragma unroll
        for (int nt = 0; nt < 2; nt++) {
            int cc = wn * 16 + nt * 8 + 2 * t;
            cs[rr][cc]         = acc[mt][nt][0];
            cs[rr][cc + 1]     = acc[mt][nt][1];
            cs[rr + 8][cc]     = acc[mt][nt][2];
            cs[rr + 8][cc + 1] = acc[mt][nt][3];
        }
    }
    __syncthreads();
    for (int i = threadIdx.x; i < 128 * 16; i += 256) {
        int row = i >> 4, c4 = (i & 15) << 2;
        int m = mb + row, n = nb + c4;
        if (m >= M) continue;
        if (n + 3 < N) {
            *(float4*)(C + (size_t)m * N + n) =
                make_float4(cs[row][c4], cs[row][c4 + 1], cs[row][c4 + 2], cs[row][c4 + 3]);
        } else {
            for (int q = 0; q < 4; q++)
                if (n + q < N) C[(size_t)m * N + n + q] = cs[row][c4 + q];
        }
    }
}

// ---------------- launch ----------------
#define SYMP(var, T, sym) do { void* _p; cudaGetSymbolAddress(&_p, sym); var = (T*)_p; } while (0)

extern "C" void kernel_launch(void* const* d_in, const int* in_sizes, int n_in,
                              void* d_out, int out_size)
{
    const float* feat_g = (const float*)d_in[0];
    const float* feat_d = (const float*)d_in[1];
    const int* gg_src = (const int*)d_in[2];
    const int* gg_dst = (const int*)d_in[3];
    const int* gd_src = (const int*)d_in[4];
    const int* gd_dst = (const int*)d_in[5];
    const int* dd_src = (const int*)d_in[6];
    const int* dd_dst = (const int*)d_in[7];
    const float* Wg   = (const float*)d_in[8];
    const float* Wd   = (const float*)d_in[9];
    const float* W1   = (const float*)d_in[10];
    const float* b1   = (const float*)d_in[11];
    const float* W2   = (const float*)d_in[12];
    const float* b2   = (const float*)d_in[13];
    const float* Wout = (const float*)d_in[14];
    const int n_gg = in_sizes[2], n_gd = in_sizes[4], n_dd = in_sizes[6];

    int *rp_gg, *rp_dg, *rp_gd, *rp_dd;
    int *col_gg, *col_dg, *col_gd, *col_dd;
    float *rs_gg_src, *rs_gg_dst, *rs_gd_src, *rs_gd_dst, *rs_dd_src, *rs_dd_dst;
    float *hg, *hd, *og, *od;
    __half *xga, *xgb, *xda, *xdb, *ah, *al, *bh, *bl;
    SYMP(rp_gg, int, g_rp_gg); SYMP(rp_dg, int, g_rp_dg);
    SYMP(rp_gd, int, g_rp_gd); SYMP(rp_dd, int, g_rp_dd);
    SYMP(col_gg, int, g_col_gg); SYMP(col_dg, int, g_col_dg);
    SYMP(col_gd, int, g_col_gd); SYMP(col_dd, int, g_col_dd);
    SYMP(rs_gg_src, float, g_rs_gg_src); SYMP(rs_gg_dst, float, g_rs_gg_dst);
    SYMP(rs_gd_src, float, g_rs_gd_src); SYMP(rs_gd_dst, float, g_rs_gd_dst);
    SYMP(rs_dd_src, float, g_rs_dd_src); SYMP(rs_dd_dst, float, g_rs_dd_dst);
    SYMP(hg, float, g_hg); SYMP(hd, float, g_hd);
    SYMP(og, float, g_og); SYMP(od, float, g_od);
    SYMP(xga, __half, g_xga); SYMP(xgb, __half, g_xgb);
    SYMP(xda, __half, g_xda); SYMP(xdb, __half, g_xdb);
    SYMP(ah, __half, g_ah);
    al = (__half*)og;            // og free during layer-2 agg (consumed by layer-2 transform)
    bh = (__half*)hd;            // g_hd free at layer-2 agg (fp16 pair fits in its 1.28MB)
    bl = (__half*)hd + NDN * 32;

    const int embG = (NGN + 31) / 32, embD = (NDN + 31) / 32;
    const int t2G = (NGN + 15) / 16, t2D = (NDN + 15) / 16;
    const int agG = (NGN + 7) / 8, agD = (NDN + 7) / 8;

    // A) zero counters
    k_zero_counts<<<(NGN + 255) / 256, 256>>>();
    // B) degree histogram (light kernel, full occupancy)
    k_hist_all<<<1480, 256>>>(gg_src, gg_dst, gd_src, gd_dst, dd_src, dd_dst,
                              n_gg, n_gd, n_dd);
    // C) scans + rsqrt
    k_setup2<<<4 + (NGN + 1023) / 1024, 1024>>>();
    // D) CSR fill (light kernel, full occupancy)
    k_scatter_all<<<1480, 256>>>(gg_src, gg_dst, gd_src, gd_dst, dd_src, dd_dst,
                                 n_gg, n_gd, n_dd);
    // E) embeddings (both node types)
    k_embed_pair<<<embG + embD, 256>>>(feat_g, Wg, hg, NGN, feat_d, Wd, hd, NDN, embG);
    // F) layer-1 dual transform
    k_t2_pair64<<<t2G + t2D, 256>>>(
        hg, rs_gg_src, W1 + 0 * 64 * 64, rs_gd_src, W1 + 1 * 64 * 64, xga, xgb, NGN,
        hd, rs_gd_dst, W1 + 2 * 64 * 64, rs_dd_src, W1 + 3 * 64 * 64, xda, xdb, NDN, t2G);
    // G) layer-1 aggregation
    k_agg_pair64<<<agG + agD, 256>>>(
        rp_gg, col_gg, xga, rs_gg_dst, rp_dg, col_dg, xda, rs_gd_src,
        b1 + 0 * 64, b1 + 2 * 64, og, NGN,
        rp_gd, col_gd, xgb, rs_gd_dst, rp_dd, col_dd, xdb, rs_dd_dst,
        b1 + 1 * 64, b1 + 3 * 64, od, NDN, agG);
    // H) layer-2 dual transform
    k_t2_pair32<<<t2G + t2D, 256>>>(
        og, rs_gg_src, W2 + 0 * 32 * 64, rs_gd_src, W2 + 1 * 32 * 64, xga, xgb, NGN,
        od, rs_gd_dst, W2 + 2 * 32 * 64, rs_dd_src, W2 + 3 * 32 * 64, xda, xdb, NDN, t2G);
    // I) layer-2 aggregation; gene -> (Ah,Al), disease -> fused @Wout -> (Bh,Bl)
    k_agg_pair32_final<<<agG + agD, 256>>>(
        rp_gg, col_gg, xga, rs_gg_dst, rp_dg, col_dg, xda, rs_gd_src,
        b2 + 0 * 32, b2 + 2 * 32, ah, al, NGN,
        rp_gd, col_gd, xgb, rs_gd_dst, rp_dd, col_dd, xdb, rs_dd_dst,
        b2 + 1 * 32, b2 + 3 * 32, Wout, bh, bl, NDN, agG);
    // J) out = (Ah+Al) @ (Bh+Bl)^T via split-fp16 tensor cores
    dim3 grid((NDN + 63) / 64, (NGN + 127) / 128);
    k_outgemm_mma<<<grid, 256>>>(ah, al, bh, bl, (float*)d_out, NGN, NDN);
}